// round 13
// baseline (speedup 1.0000x reference)
#include <cuda_runtime.h>
#include <cuda_fp16.h>
#include <cstdint>
#include <math.h>

#define N 8192
#define D 512
#define BM 128
#define NT (N / BM)                 // 64
#define NPAIRS (NT * (NT + 1) / 2)  // 2080
#define GRID 296                    // persistent CTAs, 2 per SM
#define BKC 128                     // fp8 K elements per chunk (128B rows)
#define NCHUNKS (D / BKC)           // 4
#define TILE_BYTES (BM * BKC)       // 16384
#define SMEM_BYTES (1024 + 6 * TILE_BYTES)
#define QMAX 28.0f                  // fp8 target max; keeps f16 dot_q < 65504

__device__ uint8_t g_q[N * D];
__device__ float   g_scale[N];
__device__ double  g_accum;

// ---------------------------------------------------------------------------
// PTX helpers (arch-agnostic)
// ---------------------------------------------------------------------------
__device__ __forceinline__ uint32_t smem_u32(const void* p) {
    uint32_t a;
    asm("{ .reg .u64 t; cvta.to.shared.u64 t, %1; cvt.u32.u64 %0, t; }" : "=r"(a) : "l"(p));
    return a;
}
__device__ __forceinline__ void cp16(uint32_t saddr, const void* g) {
    asm volatile("cp.async.cg.shared.global [%0], [%1], 16;" :: "r"(saddr), "l"(g) : "memory");
}
__device__ __forceinline__ void cp_commit() {
    asm volatile("cp.async.commit_group;" ::: "memory");
}
template <int NN>
__device__ __forceinline__ void cp_wait() {
    asm volatile("cp.async.wait_group %0;" :: "n"(NN) : "memory");
}
__device__ __forceinline__ void ldsm_x4(uint32_t* r, uint32_t addr) {
    asm volatile("ldmatrix.sync.aligned.m8n8.x4.shared.b16 {%0,%1,%2,%3}, [%4];"
                 : "=r"(r[0]), "=r"(r[1]), "=r"(r[2]), "=r"(r[3]) : "r"(addr));
}
__device__ __forceinline__ void qmma16832_f16(uint32_t* d, const uint32_t* a,
                                              uint32_t b0, uint32_t b1) {
    asm volatile(
        "mma.sync.aligned.m16n8k32.row.col.f16.e4m3.e4m3.f16 "
        "{%0,%1}, {%2,%3,%4,%5}, {%6,%7}, {%0,%1};"
        : "+r"(d[0]), "+r"(d[1])
        : "r"(a[0]), "r"(a[1]), "r"(a[2]), "r"(a[3]), "r"(b0), "r"(b1));
}
__device__ __forceinline__ uint32_t cvt_e4m3x2(float hi, float lo) {
    uint16_t h;
    asm("cvt.rn.satfinite.e4m3x2.f32 %0, %1, %2;" : "=h"(h) : "f"(hi), "f"(lo));
    return (uint32_t)h;
}
__device__ __forceinline__ void decode_tile(int b, int& bi, int& bj) {
    int j = (int)((sqrtf(8.0f * (float)b + 1.0f) - 1.0f) * 0.5f);
    while ((j + 1) * (j + 2) / 2 <= b) j++;
    while (j * (j + 1) / 2 > b) j--;
    bi = b - j * (j + 1) / 2;
    bj = j;
}

// ---------------------------------------------------------------------------
// Kernel 1: row L2-normalize + e4m3 quantize (qmax = QMAX). One WARP per row.
// ---------------------------------------------------------------------------
__global__ __launch_bounds__(256) void quantize_kernel(const float* __restrict__ in) {
    int row  = blockIdx.x * 8 + (threadIdx.x >> 5);
    int lane = threadIdx.x & 31;
    if (blockIdx.x == 0 && threadIdx.x == 0) g_accum = 0.0;

    const float4* src = (const float4*)(in + (size_t)row * D);
    float4 v[4];
    float ss = 0.0f;
    #pragma unroll
    for (int i = 0; i < 4; i++) {
        v[i] = src[i * 32 + lane];
        ss += v[i].x * v[i].x + v[i].y * v[i].y + v[i].z * v[i].z + v[i].w * v[i].w;
    }
    #pragma unroll
    for (int o = 16; o; o >>= 1) ss += __shfl_xor_sync(0xffffffffu, ss, o);
    float inv = rsqrtf(ss);

    float amax = 0.0f;
    #pragma unroll
    for (int i = 0; i < 4; i++)
        amax = fmaxf(amax, fmaxf(fmaxf(fabsf(v[i].x), fabsf(v[i].y)),
                                 fmaxf(fabsf(v[i].z), fabsf(v[i].w))));
    amax *= inv;
    #pragma unroll
    for (int o = 16; o; o >>= 1) amax = fmaxf(amax, __shfl_xor_sync(0xffffffffu, amax, o));

    float s    = amax * (1.0f / QMAX);
    float qmul = inv * (QMAX / amax);
    if (lane == 0) g_scale[row] = s;

    uint32_t* dq = (uint32_t*)(g_q + (size_t)row * D);
    #pragma unroll
    for (int i = 0; i < 4; i++) {
        uint32_t l16 = cvt_e4m3x2(v[i].y * qmul, v[i].x * qmul);
        uint32_t h16 = cvt_e4m3x2(v[i].w * qmul, v[i].z * qmul);
        dq[i * 32 + lane] = l16 | (h16 << 16);
    }
}

// ---------------------------------------------------------------------------
// Kernel 2: PERSISTENT upper-triangle Gram. 296 CTAs; CTA b does tiles
// b, b+296, ... The 3-stage cp.async ring runs continuously across tile
// boundaries (prefetch distance 2 chunks); epilogues overlap next tile loads.
// ---------------------------------------------------------------------------
extern __shared__ char dynsmem[];

__global__ __launch_bounds__(256, 2) void gram_persistent_kernel() {
    int t      = threadIdx.x;
    int wid    = t >> 5;
    int lane   = t & 31;
    int warp_m = wid & 1;
    int warp_n = wid >> 1;

    uint32_t smem0 = smem_u32(dynsmem);
    uint32_t base  = (smem0 + 1023) & ~1023u;
    uint32_t sA[3], sB[3];
    #pragma unroll
    for (int s = 0; s < 3; s++) {
        sA[s] = base + (2 * s)     * TILE_BYTES;
        sB[s] = base + (2 * s + 1) * TILE_BYTES;
    }

    // ---- ldsm constants: addr(kk) = stage + C ^ (kk<<5) ----
    int r7   = lane & 7;
    int a_kh = lane >> 4;
    uint32_t swz = (uint32_t)(((a_kh ^ (r7 & 1)) << 4) | (((r7 >> 1) & 3) << 5));
    int arow = warp_m * 64 + (lane & 15);
    int brow = warp_n * 32 + (lane & 7) + (((lane >> 3) & 1) << 3);
    uint32_t cA[4], cB[2];
    #pragma unroll
    for (int mi = 0; mi < 4; mi++) cA[mi] = (uint32_t)((arow + mi * 16) * 128) + swz;
    #pragma unroll
    for (int p = 0; p < 2; p++)   cB[p]  = (uint32_t)((brow + p * 16) * 128) + swz;

    // ---- loader constants ----
    int la_row = t >> 1;
    uint32_t soff[4];
    #pragma unroll
    for (int i = 0; i < 4; i++) {
        uint32_t c = (uint32_t)((t & 1) * 4 + i);
        soff[i] = (uint32_t)la_row * 128 + ((c ^ (la_row & 7)) << 4);
    }
    int lgofs = (t & 1) * 64;   // byte offset of this thread's first chunk in row

    // load chunk k0 of the tile whose row pointers are (pa, pb) into stage s
    auto load_chunk = [&](int s, const char* pa, const char* pb, int k0) {
        #pragma unroll
        for (int i = 0; i < 4; i++) {
            cp16(sA[s] + soff[i], pa + k0 + lgofs + i * 16);
            cp16(sB[s] + soff[i], pb + k0 + lgofs + i * 16);
        }
    };

    float local = 0.0f;
    int   my = blockIdx.x;

    int bi, bj;
    decode_tile(my, bi, bj);
    const char* pa = (const char*)(g_q + ((size_t)bi * BM + la_row) * D);
    const char* pb = (const char*)(g_q + ((size_t)bj * BM + la_row) * D);

    // prologue: chunks 0 and 1 of first tile
    load_chunk(0, pa, pb, 0);
    cp_commit();
    load_chunk(1, pa, pb, BKC);
    cp_commit();

    int st = 0;   // ring stage of the chunk about to be computed

    uint32_t Af[2][4][4], Bf[2][2][4];

    while (my < NPAIRS) {
        const bool diag = (bi == bj);
        int nxt = my + GRID;
        int bi2 = 0, bj2 = 0;
        const char *pa2 = pa, *pb2 = pb;
        const bool hasNext = (nxt < NPAIRS);
        if (hasNext) {
            decode_tile(nxt, bi2, bj2);
            pa2 = (const char*)(g_q + ((size_t)bi2 * BM + la_row) * D);
            pb2 = (const char*)(g_q + ((size_t)bj2 * BM + la_row) * D);
        }

        uint32_t acc[4][4][2];
        #pragma unroll
        for (int mi = 0; mi < 4; mi++)
            #pragma unroll
            for (int nj = 0; nj < 4; nj++) { acc[mi][nj][0] = 0u; acc[mi][nj][1] = 0u; }

        #pragma unroll
        for (int c = 0; c < NCHUNKS; c++) {
            cp_wait<1>();          // chunk c's group complete
            __syncthreads();       // stage (st+2)%3 free for overwrite

            // prefetch chunk c+2 (same tile, or chunks 0/1 of next tile)
            int pf = c + 2;
            if (pf < NCHUNKS)       load_chunk((st + 2) % 3, pa,  pb,  pf * BKC);
            else if (hasNext)       load_chunk((st + 2) % 3, pa2, pb2, (pf - NCHUNKS) * BKC);
            cp_commit();           // empty group at the tail keeps counts aligned

            uint32_t aBase = sA[st], bBase = sB[st];
            uint32_t eA[4], eB[2];
            #pragma unroll
            for (int mi = 0; mi < 4; mi++) eA[mi] = aBase + cA[mi];
            #pragma unroll
            for (int p = 0; p < 2; p++)   eB[p]  = bBase + cB[p];

            #pragma unroll
            for (int mi = 0; mi < 4; mi++) ldsm_x4(Af[0][mi], eA[mi]);
            #pragma unroll
            for (int p = 0; p < 2; p++)    ldsm_x4(Bf[0][p],  eB[p]);

            #pragma unroll
            for (int kk = 0; kk < 4; kk++) {
                int cur = kk & 1;
                if (kk < 3) {
                    uint32_t x = (uint32_t)((kk + 1) << 5);
                    #pragma unroll
                    for (int mi = 0; mi < 4; mi++) ldsm_x4(Af[cur ^ 1][mi], eA[mi] ^ x);
                    #pragma unroll
                    for (int p = 0; p < 2; p++)    ldsm_x4(Bf[cur ^ 1][p],  eB[p] ^ x);
                }
                #pragma unroll
                for (int mi = 0; mi < 4; mi++)
                    #pragma unroll
                    for (int nj = 0; nj < 4; nj++)
                        qmma16832_f16(acc[mi][nj], Af[cur][mi],
                                      Bf[cur][nj >> 1][nj & 1],
                                      Bf[cur][nj >> 1][(nj & 1) + 2]);
            }

            st = (st + 1) % 3;
        }

        // ---- epilogue: scales direct from global (L1/L2-hot) ----
        int lrow0 = warp_m * 64 + (lane >> 2);
        int lcol0 = warp_n * 32 + (lane & 3) * 2;
        const float* scA = g_scale + bi * BM;
        const float* scB = g_scale + bj * BM;

        float si[4][2], sj[4][2];
        #pragma unroll
        for (int mi = 0; mi < 4; mi++)
            #pragma unroll
            for (int h = 0; h < 2; h++)
                si[mi][h] = __ldg(scA + lrow0 + mi * 16 + h * 8);
        #pragma unroll
        for (int nj = 0; nj < 4; nj++)
            #pragma unroll
            for (int bc = 0; bc < 2; bc++)
                sj[nj][bc] = __ldg(scB + lcol0 + nj * 8 + bc);

        #pragma unroll
        for (int mi = 0; mi < 4; mi++)
            #pragma unroll
            for (int nj = 0; nj < 4; nj++) {
                int rm = lrow0 + mi * 16;
                int cn = lcol0 + nj * 8;
                #pragma unroll
                for (int r = 0; r < 2; r++) {
                    int im = rm + r * 8;
                    float2 f2 = __half22float2(*(__half2*)&acc[mi][nj][r]);
                    float d0 = f2.x * si[mi][r] * sj[nj][0];
                    float d1 = f2.y * si[mi][r] * sj[nj][1];
                    bool ok0 = diag ? (im < cn) : true;
                    bool ok1 = diag ? (im < cn + 1) : true;
                    if (ok0 && d0 > 0.0f) local += d0;
                    if (ok1 && d1 > 0.0f) local += d1;
                }
            }

        my = nxt; bi = bi2; bj = bj2; pa = pa2; pb = pb2;
    }

    // one reduction + one atomic per CTA
    #pragma unroll
    for (int o = 16; o; o >>= 1) local += __shfl_xor_sync(0xffffffffu, local, o);
    __shared__ float red[8];
    if (lane == 0) red[wid] = local;
    __syncthreads();
    if (t == 0) {
        float s = 0.0f;
        #pragma unroll
        for (int w = 0; w < 8; w++) s += red[w];
        atomicAdd(&g_accum, (double)s);
    }
}

// ---------------------------------------------------------------------------
// Kernel 3: finalize.
// ---------------------------------------------------------------------------
__global__ void finalize_kernel(float* __restrict__ out, int out_size) {
    double v = 2.0 * g_accum / ((double)N * (double)N);
    float f = (float)v;
    out[0] = f;
    if (out_size > 1) out[1] = f;
}

extern "C" void kernel_launch(void* const* d_in, const int* in_sizes, int n_in,
                              void* d_out, int out_size) {
    const float* id = (const float*)d_in[0];
    cudaFuncSetAttribute(gram_persistent_kernel,
                         cudaFuncAttributeMaxDynamicSharedMemorySize, SMEM_BYTES);
    quantize_kernel<<<N / 8, 256>>>(id);
    gram_persistent_kernel<<<GRID, 256, SMEM_BYTES>>>();
    finalize_kernel<<<1, 1>>>((float*)d_out, out_size);
}

// round 14
// speedup vs baseline: 1.0298x; 1.0298x over previous
#include <cuda_runtime.h>
#include <cuda_fp16.h>
#include <cstdint>
#include <math.h>

#define N 8192
#define D 512
#define BM 128
#define NT (N / BM)                 // 64
#define NPAIRS (NT * (NT + 1) / 2)  // 2080
#define GRID 296                    // 2 CTAs per SM, persistent-lite
#define BKC 128                     // fp8 K elements per chunk (128B rows)
#define NCHUNKS (D / BKC)           // 4
#define NSTAGE 3
#define TILE_BYTES (BM * BKC)       // 16384
#define SMEM_BYTES (1024 + 2 * NSTAGE * TILE_BYTES)
#define QMAX 28.0f                  // fp8 target max; keeps f16 dot_q < 65504

__device__ uint8_t g_q[N * D];
__device__ float   g_scale[N];
__device__ double  g_accum;

// ---------------------------------------------------------------------------
// PTX helpers (arch-agnostic)
// ---------------------------------------------------------------------------
__device__ __forceinline__ uint32_t smem_u32(const void* p) {
    uint32_t a;
    asm("{ .reg .u64 t; cvta.to.shared.u64 t, %1; cvt.u32.u64 %0, t; }" : "=r"(a) : "l"(p));
    return a;
}
__device__ __forceinline__ void cp16(uint32_t saddr, const void* g) {
    asm volatile("cp.async.cg.shared.global [%0], [%1], 16;" :: "r"(saddr), "l"(g) : "memory");
}
__device__ __forceinline__ void cp_commit() {
    asm volatile("cp.async.commit_group;" ::: "memory");
}
template <int NN>
__device__ __forceinline__ void cp_wait() {
    asm volatile("cp.async.wait_group %0;" :: "n"(NN) : "memory");
}
__device__ __forceinline__ void ldsm_x4(uint32_t* r, uint32_t addr) {
    asm volatile("ldmatrix.sync.aligned.m8n8.x4.shared.b16 {%0,%1,%2,%3}, [%4];"
                 : "=r"(r[0]), "=r"(r[1]), "=r"(r[2]), "=r"(r[3]) : "r"(addr));
}
__device__ __forceinline__ void qmma16832_f16(uint32_t* d, const uint32_t* a,
                                              uint32_t b0, uint32_t b1) {
    asm volatile(
        "mma.sync.aligned.m16n8k32.row.col.f16.e4m3.e4m3.f16 "
        "{%0,%1}, {%2,%3,%4,%5}, {%6,%7}, {%0,%1};"
        : "+r"(d[0]), "+r"(d[1])
        : "r"(a[0]), "r"(a[1]), "r"(a[2]), "r"(a[3]), "r"(b0), "r"(b1));
}
__device__ __forceinline__ uint32_t cvt_e4m3x2(float hi, float lo) {
    uint16_t h;
    asm("cvt.rn.satfinite.e4m3x2.f32 %0, %1, %2;" : "=h"(h) : "f"(hi), "f"(lo));
    return (uint32_t)h;
}

// ---------------------------------------------------------------------------
// Kernel 1: row L2-normalize + e4m3 quantize (qmax = QMAX). One WARP per row.
// ---------------------------------------------------------------------------
__global__ __launch_bounds__(256) void quantize_kernel(const float* __restrict__ in) {
    int row  = blockIdx.x * 8 + (threadIdx.x >> 5);
    int lane = threadIdx.x & 31;
    if (blockIdx.x == 0 && threadIdx.x == 0) g_accum = 0.0;

    const float4* src = (const float4*)(in + (size_t)row * D);
    float4 v[4];
    float ss = 0.0f;
    #pragma unroll
    for (int i = 0; i < 4; i++) {
        v[i] = src[i * 32 + lane];
        ss += v[i].x * v[i].x + v[i].y * v[i].y + v[i].z * v[i].z + v[i].w * v[i].w;
    }
    #pragma unroll
    for (int o = 16; o; o >>= 1) ss += __shfl_xor_sync(0xffffffffu, ss, o);
    float inv = rsqrtf(ss);

    float amax = 0.0f;
    #pragma unroll
    for (int i = 0; i < 4; i++)
        amax = fmaxf(amax, fmaxf(fmaxf(fabsf(v[i].x), fabsf(v[i].y)),
                                 fmaxf(fabsf(v[i].z), fabsf(v[i].w))));
    amax *= inv;
    #pragma unroll
    for (int o = 16; o; o >>= 1) amax = fmaxf(amax, __shfl_xor_sync(0xffffffffu, amax, o));

    float s    = amax * (1.0f / QMAX);
    float qmul = inv * (QMAX / amax);
    if (lane == 0) g_scale[row] = s;

    uint32_t* dq = (uint32_t*)(g_q + (size_t)row * D);
    #pragma unroll
    for (int i = 0; i < 4; i++) {
        uint32_t l16 = cvt_e4m3x2(v[i].y * qmul, v[i].x * qmul);
        uint32_t h16 = cvt_e4m3x2(v[i].w * qmul, v[i].z * qmul);
        dq[i * 32 + lane] = l16 | (h16 << 16);
    }
}

// ---------------------------------------------------------------------------
// Kernel 2: persistent-lite upper-triangle Gram. 296 CTAs, each runs the
// R12 tile body for tiles bid, bid+296, ...  All stage indices inside the
// tile body are compile-time constants (fully unrolled chunk loop).
// ---------------------------------------------------------------------------
extern __shared__ char dynsmem[];

__global__ __launch_bounds__(256, 2) void gram_qmma_kernel() {
    int t      = threadIdx.x;
    int wid    = t >> 5;
    int lane   = t & 31;
    int warp_m = wid & 1;
    int warp_n = wid >> 1;

    uint32_t smem0 = smem_u32(dynsmem);
    uint32_t base  = (smem0 + 1023) & ~1023u;
    uint32_t sA[NSTAGE], sB[NSTAGE];
    #pragma unroll
    for (int s = 0; s < NSTAGE; s++) {
        sA[s] = base + (2 * s)     * TILE_BYTES;
        sB[s] = base + (2 * s + 1) * TILE_BYTES;
    }

    // ---- ldsm constants: addr(kk) = (stage + C) ^ (kk<<5) ----
    int r7   = lane & 7;
    int a_kh = lane >> 4;
    uint32_t swz = (uint32_t)(((a_kh ^ (r7 & 1)) << 4) | (((r7 >> 1) & 3) << 5));
    int arow = warp_m * 64 + (lane & 15);
    int brow = warp_n * 32 + (lane & 7) + (((lane >> 3) & 1) << 3);
    uint32_t cA[4], cB[2];
    #pragma unroll
    for (int mi = 0; mi < 4; mi++) cA[mi] = (uint32_t)((arow + mi * 16) * 128) + swz;
    #pragma unroll
    for (int p = 0; p < 2; p++)   cB[p]  = (uint32_t)((brow + p * 16) * 128) + swz;

    // ---- async tile loader offsets ----
    int la_row = t >> 1;
    uint32_t soff[4];
    #pragma unroll
    for (int i = 0; i < 4; i++) {
        uint32_t c = (uint32_t)((t & 1) * 4 + i);
        soff[i] = (uint32_t)la_row * 128 + ((c ^ (la_row & 7)) << 4);
    }
    int lgofs = (t & 1) * 64;
    int lrow0 = warp_m * 64 + (lane >> 2);
    int lcol0 = warp_n * 32 + (lane & 3) * 2;

    float local = 0.0f;

    #pragma unroll 1
    for (int tile = blockIdx.x; tile < NPAIRS; tile += GRID) {
        int bj = (int)((sqrtf(8.0f * (float)tile + 1.0f) - 1.0f) * 0.5f);
        while ((bj + 1) * (bj + 2) / 2 <= tile) bj++;
        while (bj * (bj + 1) / 2 > tile) bj--;
        int bi = tile - bj * (bj + 1) / 2;
        const bool diag = (bi == bj);

        const char* gpA = (const char*)(g_q + ((size_t)bi * BM + la_row) * D);
        const char* gpB = (const char*)(g_q + ((size_t)bj * BM + la_row) * D);

        auto load_stage = [&](int s, int k0) {
            #pragma unroll
            for (int i = 0; i < 4; i++) {
                int gofs = k0 + lgofs + i * 16;
                cp16(sA[s] + soff[i], gpA + gofs);
                cp16(sB[s] + soff[i], gpB + gofs);
            }
            cp_commit();
        };

        uint32_t acc[4][4][2];
        #pragma unroll
        for (int mi = 0; mi < 4; mi++)
            #pragma unroll
            for (int nj = 0; nj < 4; nj++) { acc[mi][nj][0] = 0u; acc[mi][nj][1] = 0u; }

        load_stage(0, 0);
        load_stage(1, BKC);

        uint32_t Af[2][4][4], Bf[2][2][4];

        #pragma unroll
        for (int c = 0; c < NCHUNKS; c++) {
            if (c < NCHUNKS - 1) cp_wait<1>(); else cp_wait<0>();
            __syncthreads();

            if (c + 2 < NCHUNKS) load_stage((c + 2) % NSTAGE, (c + 2) * BKC);

            uint32_t aBase = sA[c % NSTAGE], bBase = sB[c % NSTAGE];
            uint32_t eA[4], eB[2];
            #pragma unroll
            for (int mi = 0; mi < 4; mi++) eA[mi] = aBase + cA[mi];
            #pragma unroll
            for (int p = 0; p < 2; p++)   eB[p]  = bBase + cB[p];

            #pragma unroll
            for (int mi = 0; mi < 4; mi++) ldsm_x4(Af[0][mi], eA[mi]);
            #pragma unroll
            for (int p = 0; p < 2; p++)    ldsm_x4(Bf[0][p],  eB[p]);

            #pragma unroll
            for (int kk = 0; kk < 4; kk++) {
                int cur = kk & 1;
                if (kk < 3) {
                    uint32_t x = (uint32_t)((kk + 1) << 5);
                    #pragma unroll
                    for (int mi = 0; mi < 4; mi++) ldsm_x4(Af[cur ^ 1][mi], eA[mi] ^ x);
                    #pragma unroll
                    for (int p = 0; p < 2; p++)    ldsm_x4(Bf[cur ^ 1][p],  eB[p] ^ x);
                }
                #pragma unroll
                for (int mi = 0; mi < 4; mi++)
                    #pragma unroll
                    for (int nj = 0; nj < 4; nj++)
                        qmma16832_f16(acc[mi][nj], Af[cur][mi],
                                      Bf[cur][nj >> 1][nj & 1],
                                      Bf[cur][nj >> 1][(nj & 1) + 2]);
            }
        }

        // ---- epilogue: scale (s_i*s_j), relu, strict-upper mask ----
        const float* scA = g_scale + bi * BM;
        const float* scB = g_scale + bj * BM;
        float si[4][2], sj[4][2];
        #pragma unroll
        for (int mi = 0; mi < 4; mi++)
            #pragma unroll
            for (int h = 0; h < 2; h++)
                si[mi][h] = __ldg(scA + lrow0 + mi * 16 + h * 8);
        #pragma unroll
        for (int nj = 0; nj < 4; nj++)
            #pragma unroll
            for (int bc = 0; bc < 2; bc++)
                sj[nj][bc] = __ldg(scB + lcol0 + nj * 8 + bc);

        #pragma unroll
        for (int mi = 0; mi < 4; mi++)
            #pragma unroll
            for (int nj = 0; nj < 4; nj++) {
                int rm = lrow0 + mi * 16;
                int cn = lcol0 + nj * 8;
                #pragma unroll
                for (int r = 0; r < 2; r++) {
                    int im = rm + r * 8;
                    float2 f2 = __half22float2(*(__half2*)&acc[mi][nj][r]);
                    float d0 = f2.x * si[mi][r] * sj[nj][0];
                    float d1 = f2.y * si[mi][r] * sj[nj][1];
                    bool ok0 = diag ? (im < cn) : true;
                    bool ok1 = diag ? (im < cn + 1) : true;
                    if (ok0 && d0 > 0.0f) local += d0;
                    if (ok1 && d1 > 0.0f) local += d1;
                }
            }
    }

    // one reduction + one atomic per CTA
    #pragma unroll
    for (int o = 16; o; o >>= 1) local += __shfl_xor_sync(0xffffffffu, local, o);
    __shared__ float red[8];
    if (lane == 0) red[wid] = local;
    __syncthreads();
    if (t == 0) {
        float s = 0.0f;
        #pragma unroll
        for (int w = 0; w < 8; w++) s += red[w];
        atomicAdd(&g_accum, (double)s);
    }
}

// ---------------------------------------------------------------------------
// Kernel 3: finalize.
// ---------------------------------------------------------------------------
__global__ void finalize_kernel(float* __restrict__ out, int out_size) {
    double v = 2.0 * g_accum / ((double)N * (double)N);
    float f = (float)v;
    out[0] = f;
    if (out_size > 1) out[1] = f;
}

extern "C" void kernel_launch(void* const* d_in, const int* in_sizes, int n_in,
                              void* d_out, int out_size) {
    const float* id = (const float*)d_in[0];
    cudaFuncSetAttribute(gram_qmma_kernel, cudaFuncAttributeMaxDynamicSharedMemorySize,
                         SMEM_BYTES);
    quantize_kernel<<<N / 8, 256>>>(id);
    gram_qmma_kernel<<<GRID, 256, SMEM_BYTES>>>();
    finalize_kernel<<<1, 1>>>((float*)d_out, out_size);
}